// round 3
// baseline (speedup 1.0000x reference)
#include <cuda_runtime.h>
#include <cuda_bf16.h>

#define NUM_GRAPHS 512
#define C 128
#define CG (C / 4)        // 32 channel-groups of float4
#define THREADS 512
#define ROWS_PER_ITER (THREADS / CG)   // 16
#define EPS 1e-5f
#define GRID 148

// Segment start offsets: starts[g] = first row index with batch >= g; starts[512] = N.
__device__ int g_starts[NUM_GRAPHS + 1];

// batch is int32 on device (JAX x64 disabled => astype(int64) yields int32).
__global__ void find_starts_kernel(const int* __restrict__ batch, int n) {
    int g = threadIdx.x;
    if (g > NUM_GRAPHS) return;
    int lo = 0, hi = n;
    while (lo < hi) {
        int mid = (lo + hi) >> 1;
        if (batch[mid] < g) lo = mid + 1; else hi = mid;
    }
    g_starts[g] = lo;
}

__global__ __launch_bounds__(THREADS)
void graphnorm_kernel(const float* __restrict__ x,
                      const float* __restrict__ weight,
                      const float* __restrict__ bias,
                      float* __restrict__ out) {
    const int t  = threadIdx.x;
    const int cg = t & (CG - 1);   // channel group (4 consecutive channels)
    const int rw = t >> 5;         // row lane within iteration (0..15)

    __shared__ float s_sum[ROWS_PER_ITER][C];   // 8 KB
    __shared__ float s_sq [ROWS_PER_ITER][C];   // 8 KB
    __shared__ float s_mean[C];
    __shared__ float s_inv [C];

    const float4 wv = ((const float4*)weight)[cg];
    const float4 bv = ((const float4*)bias)[cg];

    const float4* __restrict__ xp  = (const float4*)x;
    float4* __restrict__       op  = (float4*)out;

    for (int g = blockIdx.x; g < NUM_GRAPHS; g += gridDim.x) {
        const int start = g_starts[g];
        const int end   = g_starts[g + 1];
        const int cnt   = end - start;

        // ---- pass 1: per-thread register accumulation (deterministic order) ----
        float s0 = 0.f, s1 = 0.f, s2 = 0.f, s3 = 0.f;
        float q0 = 0.f, q1 = 0.f, q2 = 0.f, q3 = 0.f;
        #pragma unroll 4
        for (int r = start + rw; r < end; r += ROWS_PER_ITER) {
            float4 v = xp[(size_t)r * CG + cg];
            s0 += v.x; s1 += v.y; s2 += v.z; s3 += v.w;
            q0 += v.x * v.x; q1 += v.y * v.y; q2 += v.z * v.z; q3 += v.w * v.w;
        }
        s_sum[rw][cg * 4 + 0] = s0; s_sum[rw][cg * 4 + 1] = s1;
        s_sum[rw][cg * 4 + 2] = s2; s_sum[rw][cg * 4 + 3] = s3;
        s_sq [rw][cg * 4 + 0] = q0; s_sq [rw][cg * 4 + 1] = q1;
        s_sq [rw][cg * 4 + 2] = q2; s_sq [rw][cg * 4 + 3] = q3;
        __syncthreads();

        // ---- cross-lane reduction (32 threads, fixed order => deterministic) ----
        if (rw == 0) {
            float S0 = 0.f, S1 = 0.f, S2 = 0.f, S3 = 0.f;
            float Q0 = 0.f, Q1 = 0.f, Q2 = 0.f, Q3 = 0.f;
            #pragma unroll
            for (int k = 0; k < ROWS_PER_ITER; k++) {
                S0 += s_sum[k][cg * 4 + 0]; S1 += s_sum[k][cg * 4 + 1];
                S2 += s_sum[k][cg * 4 + 2]; S3 += s_sum[k][cg * 4 + 3];
                Q0 += s_sq [k][cg * 4 + 0]; Q1 += s_sq [k][cg * 4 + 1];
                Q2 += s_sq [k][cg * 4 + 2]; Q3 += s_sq [k][cg * 4 + 3];
            }
            const float invc = 1.0f / (float)max(cnt, 1);
            float m0 = S0 * invc, m1 = S1 * invc, m2 = S2 * invc, m3 = S3 * invc;
            float v0 = Q0 * invc - m0 * m0;
            float v1 = Q1 * invc - m1 * m1;
            float v2 = Q2 * invc - m2 * m2;
            float v3 = Q3 * invc - m3 * m3;
            s_mean[cg * 4 + 0] = m0; s_mean[cg * 4 + 1] = m1;
            s_mean[cg * 4 + 2] = m2; s_mean[cg * 4 + 3] = m3;
            s_inv [cg * 4 + 0] = rsqrtf(v0 + EPS);
            s_inv [cg * 4 + 1] = rsqrtf(v1 + EPS);
            s_inv [cg * 4 + 2] = rsqrtf(v2 + EPS);
            s_inv [cg * 4 + 3] = rsqrtf(v3 + EPS);
        }
        __syncthreads();

        const float4 m  = ((const float4*)s_mean)[cg];
        const float4 iv = ((const float4*)s_inv)[cg];

        // ---- pass 2: normalize; x re-read should hit L2, stores stream past L2 ----
        #pragma unroll 4
        for (int r = start + rw; r < end; r += ROWS_PER_ITER) {
            float4 v = xp[(size_t)r * CG + cg];
            v.x = (v.x - m.x) * iv.x * wv.x + bv.x;
            v.y = (v.y - m.y) * iv.y * wv.y + bv.y;
            v.z = (v.z - m.z) * iv.z * wv.z + bv.z;
            v.w = (v.w - m.w) * iv.w * wv.w + bv.w;
            __stcs(&op[(size_t)r * CG + cg], v);
        }
        __syncthreads();   // protect smem before next segment's writes
    }
}

extern "C" void kernel_launch(void* const* d_in, const int* in_sizes, int n_in,
                              void* d_out, int out_size) {
    const float* x      = (const float*)d_in[0];
    const int*   batch  = (const int*)d_in[1];
    const float* weight = (const float*)d_in[2];
    const float* bias   = (const float*)d_in[3];
    float*       out    = (float*)d_out;
    const int n = in_sizes[1];   // number of rows (batch has one entry per row)

    find_starts_kernel<<<1, NUM_GRAPHS + 1>>>(batch, n);
    graphnorm_kernel<<<GRID, THREADS>>>(x, weight, bias, out);
}

// round 4
// speedup vs baseline: 1.3992x; 1.3992x over previous
#include <cuda_runtime.h>
#include <cuda_bf16.h>

#define NUM_GRAPHS 512
#define C 128
#define CG (C / 4)        // 32 channel-groups of float4
#define THREADS 512
#define ROWS_PER_ITER (THREADS / CG)   // 16
#define EPS 1e-5f
#define GRID 256          // 2 CTAs/SM resident, 2 segments per CTA

// Segment start offsets: starts[g] = first row index with batch >= g; starts[512] = N.
__device__ int g_starts[NUM_GRAPHS + 1];

// batch is int32 on device (JAX x64 disabled => astype(int64) yields int32).
__global__ void find_starts_kernel(const int* __restrict__ batch, int n) {
    int g = threadIdx.x;
    if (g > NUM_GRAPHS) return;
    int lo = 0, hi = n;
    while (lo < hi) {
        int mid = (lo + hi) >> 1;
        if (batch[mid] < g) lo = mid + 1; else hi = mid;
    }
    g_starts[g] = lo;
}

__global__ __launch_bounds__(THREADS, 2)
void graphnorm_kernel(const float* __restrict__ x,
                      const float* __restrict__ weight,
                      const float* __restrict__ bias,
                      float* __restrict__ out) {
    const int t  = threadIdx.x;
    const int cg = t & (CG - 1);   // channel group (4 consecutive channels)
    const int rw = t >> 5;         // row lane within iteration (0..15)

    __shared__ float s_sum[ROWS_PER_ITER][C];   // 8 KB
    __shared__ float s_sq [ROWS_PER_ITER][C];   // 8 KB
    __shared__ float s_mean[C];
    __shared__ float s_inv [C];

    const float4 wv = ((const float4*)weight)[cg];
    const float4 bv = ((const float4*)bias)[cg];

    const float4* __restrict__ xp  = (const float4*)x;
    float4* __restrict__       op  = (float4*)out;

    for (int g = blockIdx.x; g < NUM_GRAPHS; g += GRID) {
        const int start = g_starts[g];
        const int end   = g_starts[g + 1];
        const int cnt   = end - start;

        // ---- pass 1: 4-way batched loads, per-thread register accumulation ----
        float s0 = 0.f, s1 = 0.f, s2 = 0.f, s3 = 0.f;
        float q0 = 0.f, q1 = 0.f, q2 = 0.f, q3 = 0.f;
        int r = start + rw;
        for (; r + 3 * ROWS_PER_ITER < end; r += 4 * ROWS_PER_ITER) {
            // four independent LDG.128 in flight before any dependent math
            float4 a = xp[(size_t)r * CG + cg];
            float4 b = xp[(size_t)(r + 1 * ROWS_PER_ITER) * CG + cg];
            float4 c = xp[(size_t)(r + 2 * ROWS_PER_ITER) * CG + cg];
            float4 d = xp[(size_t)(r + 3 * ROWS_PER_ITER) * CG + cg];
            s0 += a.x; s1 += a.y; s2 += a.z; s3 += a.w;
            q0 += a.x * a.x; q1 += a.y * a.y; q2 += a.z * a.z; q3 += a.w * a.w;
            s0 += b.x; s1 += b.y; s2 += b.z; s3 += b.w;
            q0 += b.x * b.x; q1 += b.y * b.y; q2 += b.z * b.z; q3 += b.w * b.w;
            s0 += c.x; s1 += c.y; s2 += c.z; s3 += c.w;
            q0 += c.x * c.x; q1 += c.y * c.y; q2 += c.z * c.z; q3 += c.w * c.w;
            s0 += d.x; s1 += d.y; s2 += d.z; s3 += d.w;
            q0 += d.x * d.x; q1 += d.y * d.y; q2 += d.z * d.z; q3 += d.w * d.w;
        }
        for (; r < end; r += ROWS_PER_ITER) {
            float4 v = xp[(size_t)r * CG + cg];
            s0 += v.x; s1 += v.y; s2 += v.z; s3 += v.w;
            q0 += v.x * v.x; q1 += v.y * v.y; q2 += v.z * v.z; q3 += v.w * v.w;
        }
        s_sum[rw][cg * 4 + 0] = s0; s_sum[rw][cg * 4 + 1] = s1;
        s_sum[rw][cg * 4 + 2] = s2; s_sum[rw][cg * 4 + 3] = s3;
        s_sq [rw][cg * 4 + 0] = q0; s_sq [rw][cg * 4 + 1] = q1;
        s_sq [rw][cg * 4 + 2] = q2; s_sq [rw][cg * 4 + 3] = q3;
        __syncthreads();

        // ---- cross-lane reduction (32 threads, fixed order => deterministic) ----
        if (rw == 0) {
            float S0 = 0.f, S1 = 0.f, S2 = 0.f, S3 = 0.f;
            float Q0 = 0.f, Q1 = 0.f, Q2 = 0.f, Q3 = 0.f;
            #pragma unroll
            for (int k = 0; k < ROWS_PER_ITER; k++) {
                S0 += s_sum[k][cg * 4 + 0]; S1 += s_sum[k][cg * 4 + 1];
                S2 += s_sum[k][cg * 4 + 2]; S3 += s_sum[k][cg * 4 + 3];
                Q0 += s_sq [k][cg * 4 + 0]; Q1 += s_sq [k][cg * 4 + 1];
                Q2 += s_sq [k][cg * 4 + 2]; Q3 += s_sq [k][cg * 4 + 3];
            }
            const float invc = 1.0f / (float)max(cnt, 1);
            float m0 = S0 * invc, m1 = S1 * invc, m2 = S2 * invc, m3 = S3 * invc;
            float v0 = Q0 * invc - m0 * m0;
            float v1 = Q1 * invc - m1 * m1;
            float v2 = Q2 * invc - m2 * m2;
            float v3 = Q3 * invc - m3 * m3;
            s_mean[cg * 4 + 0] = m0; s_mean[cg * 4 + 1] = m1;
            s_mean[cg * 4 + 2] = m2; s_mean[cg * 4 + 3] = m3;
            s_inv [cg * 4 + 0] = rsqrtf(v0 + EPS);
            s_inv [cg * 4 + 1] = rsqrtf(v1 + EPS);
            s_inv [cg * 4 + 2] = rsqrtf(v2 + EPS);
            s_inv [cg * 4 + 3] = rsqrtf(v3 + EPS);
        }
        __syncthreads();

        const float4 m  = ((const float4*)s_mean)[cg];
        const float4 iv = ((const float4*)s_inv)[cg];

        // ---- pass 2: normalize; x re-read hits L2, stores stream past L2 ----
        r = start + rw;
        for (; r + 3 * ROWS_PER_ITER < end; r += 4 * ROWS_PER_ITER) {
            float4 a = xp[(size_t)r * CG + cg];
            float4 b = xp[(size_t)(r + 1 * ROWS_PER_ITER) * CG + cg];
            float4 c = xp[(size_t)(r + 2 * ROWS_PER_ITER) * CG + cg];
            float4 d = xp[(size_t)(r + 3 * ROWS_PER_ITER) * CG + cg];
            a.x = (a.x - m.x) * iv.x * wv.x + bv.x;
            a.y = (a.y - m.y) * iv.y * wv.y + bv.y;
            a.z = (a.z - m.z) * iv.z * wv.z + bv.z;
            a.w = (a.w - m.w) * iv.w * wv.w + bv.w;
            __stcs(&op[(size_t)r * CG + cg], a);
            b.x = (b.x - m.x) * iv.x * wv.x + bv.x;
            b.y = (b.y - m.y) * iv.y * wv.y + bv.y;
            b.z = (b.z - m.z) * iv.z * wv.z + bv.z;
            b.w = (b.w - m.w) * iv.w * wv.w + bv.w;
            __stcs(&op[(size_t)(r + 1 * ROWS_PER_ITER) * CG + cg], b);
            c.x = (c.x - m.x) * iv.x * wv.x + bv.x;
            c.y = (c.y - m.y) * iv.y * wv.y + bv.y;
            c.z = (c.z - m.z) * iv.z * wv.z + bv.z;
            c.w = (c.w - m.w) * iv.w * wv.w + bv.w;
            __stcs(&op[(size_t)(r + 2 * ROWS_PER_ITER) * CG + cg], c);
            d.x = (d.x - m.x) * iv.x * wv.x + bv.x;
            d.y = (d.y - m.y) * iv.y * wv.y + bv.y;
            d.z = (d.z - m.z) * iv.z * wv.z + bv.z;
            d.w = (d.w - m.w) * iv.w * wv.w + bv.w;
            __stcs(&op[(size_t)(r + 3 * ROWS_PER_ITER) * CG + cg], d);
        }
        for (; r < end; r += ROWS_PER_ITER) {
            float4 v = xp[(size_t)r * CG + cg];
            v.x = (v.x - m.x) * iv.x * wv.x + bv.x;
            v.y = (v.y - m.y) * iv.y * wv.y + bv.y;
            v.z = (v.z - m.z) * iv.z * wv.z + bv.z;
            v.w = (v.w - m.w) * iv.w * wv.w + bv.w;
            __stcs(&op[(size_t)r * CG + cg], v);
        }
        __syncthreads();   // protect smem before next segment's writes
    }
}

extern "C" void kernel_launch(void* const* d_in, const int* in_sizes, int n_in,
                              void* d_out, int out_size) {
    const float* x      = (const float*)d_in[0];
    const int*   batch  = (const int*)d_in[1];
    const float* weight = (const float*)d_in[2];
    const float* bias   = (const float*)d_in[3];
    float*       out    = (float*)d_out;
    const int n = in_sizes[1];   // number of rows (batch has one entry per row)

    find_starts_kernel<<<1, NUM_GRAPHS + 1>>>(batch, n);
    graphnorm_kernel<<<GRID, THREADS>>>(x, weight, bias, out);
}

// round 6
// speedup vs baseline: 1.5451x; 1.1043x over previous
#include <cuda_runtime.h>
#include <cuda_bf16.h>

#define NUM_GRAPHS 512
#define C 128
#define CG (C / 4)        // 32 channel-groups of float4
#define THREADS 512
#define ROWS_PER_ITER (THREADS / CG)   // 16
#define EPS 1e-5f
#define GRID 256
#define NPAIRS (GRID / 2)              // 128 pairs; 2 CTAs cooperate per segment
#define NSEG_ITERS (NUM_GRAPHS / NPAIRS)  // 4 segments per pair

__global__ __launch_bounds__(THREADS, 2)
void graphnorm_kernel(const float* __restrict__ x,
                      const int*   __restrict__ batch,
                      const float* __restrict__ weight,
                      const float* __restrict__ bias,
                      float* __restrict__ out,
                      int n) {
    const int t    = threadIdx.x;
    const int cg   = t & (CG - 1);   // channel group (4 consecutive channels)
    const int rw   = t >> 5;         // row lane within iteration (0..15)
    const int pair = blockIdx.x >> 1;
    const int half = blockIdx.x & 1;

    __shared__ int   s_bound[2 * NSEG_ITERS];
    __shared__ float s_sum[ROWS_PER_ITER][C];   // 8 KB
    __shared__ float s_sq [ROWS_PER_ITER][C];   // 8 KB
    __shared__ float s_mean[C];
    __shared__ float s_inv [C];

    // ---- fused boundary search: threads 0..7 each find one segment boundary ----
    if (t < 2 * NSEG_ITERS) {
        const int g = pair + (t >> 1) * NPAIRS + (t & 1);   // starts[g]
        int lo = 0, hi = n;
        while (lo < hi) {
            int mid = (lo + hi) >> 1;
            if (batch[mid] < g) lo = mid + 1; else hi = mid;
        }
        s_bound[t] = lo;
    }

    const float4 wv = ((const float4*)weight)[cg];
    const float4 bv = ((const float4*)bias)[cg];
    const float4* __restrict__ xp = (const float4*)x;
    float4* __restrict__       op = (float4*)out;

    __syncthreads();

    for (int i = 0; i < NSEG_ITERS; i++) {
        const int start = s_bound[2 * i];
        const int end   = s_bound[2 * i + 1];
        const int cnt   = end - start;

        // ---- pass 1: BOTH CTAs of the pair compute full-segment stats ----
        // (identical order => bit-identical results; 2nd reader hits L2)
        float s0 = 0.f, s1 = 0.f, s2 = 0.f, s3 = 0.f;
        float q0 = 0.f, q1 = 0.f, q2 = 0.f, q3 = 0.f;
        int r = start + rw;
        for (; r + 3 * ROWS_PER_ITER < end; r += 4 * ROWS_PER_ITER) {
            float4 a = xp[(size_t)r * CG + cg];
            float4 b = xp[(size_t)(r + 1 * ROWS_PER_ITER) * CG + cg];
            float4 c = xp[(size_t)(r + 2 * ROWS_PER_ITER) * CG + cg];
            float4 d = xp[(size_t)(r + 3 * ROWS_PER_ITER) * CG + cg];
            s0 += a.x; s1 += a.y; s2 += a.z; s3 += a.w;
            q0 += a.x * a.x; q1 += a.y * a.y; q2 += a.z * a.z; q3 += a.w * a.w;
            s0 += b.x; s1 += b.y; s2 += b.z; s3 += b.w;
            q0 += b.x * b.x; q1 += b.y * b.y; q2 += b.z * b.z; q3 += b.w * b.w;
            s0 += c.x; s1 += c.y; s2 += c.z; s3 += c.w;
            q0 += c.x * c.x; q1 += c.y * c.y; q2 += c.z * c.z; q3 += c.w * c.w;
            s0 += d.x; s1 += d.y; s2 += d.z; s3 += d.w;
            q0 += d.x * d.x; q1 += d.y * d.y; q2 += d.z * d.z; q3 += d.w * d.w;
        }
        for (; r < end; r += ROWS_PER_ITER) {
            float4 v = xp[(size_t)r * CG + cg];
            s0 += v.x; s1 += v.y; s2 += v.z; s3 += v.w;
            q0 += v.x * v.x; q1 += v.y * v.y; q2 += v.z * v.z; q3 += v.w * v.w;
        }
        s_sum[rw][cg * 4 + 0] = s0; s_sum[rw][cg * 4 + 1] = s1;
        s_sum[rw][cg * 4 + 2] = s2; s_sum[rw][cg * 4 + 3] = s3;
        s_sq [rw][cg * 4 + 0] = q0; s_sq [rw][cg * 4 + 1] = q1;
        s_sq [rw][cg * 4 + 2] = q2; s_sq [rw][cg * 4 + 3] = q3;
        __syncthreads();

        // ---- cross-lane reduction (fixed order => deterministic) ----
        if (rw == 0) {
            float S0 = 0.f, S1 = 0.f, S2 = 0.f, S3 = 0.f;
            float Q0 = 0.f, Q1 = 0.f, Q2 = 0.f, Q3 = 0.f;
            #pragma unroll
            for (int k = 0; k < ROWS_PER_ITER; k++) {
                S0 += s_sum[k][cg * 4 + 0]; S1 += s_sum[k][cg * 4 + 1];
                S2 += s_sum[k][cg * 4 + 2]; S3 += s_sum[k][cg * 4 + 3];
                Q0 += s_sq [k][cg * 4 + 0]; Q1 += s_sq [k][cg * 4 + 1];
                Q2 += s_sq [k][cg * 4 + 2]; Q3 += s_sq [k][cg * 4 + 3];
            }
            const float invc = 1.0f / (float)max(cnt, 1);
            float m0 = S0 * invc, m1 = S1 * invc, m2 = S2 * invc, m3 = S3 * invc;
            float v0 = Q0 * invc - m0 * m0;
            float v1 = Q1 * invc - m1 * m1;
            float v2 = Q2 * invc - m2 * m2;
            float v3 = Q3 * invc - m3 * m3;
            s_mean[cg * 4 + 0] = m0; s_mean[cg * 4 + 1] = m1;
            s_mean[cg * 4 + 2] = m2; s_mean[cg * 4 + 3] = m3;
            s_inv [cg * 4 + 0] = rsqrtf(v0 + EPS);
            s_inv [cg * 4 + 1] = rsqrtf(v1 + EPS);
            s_inv [cg * 4 + 2] = rsqrtf(v2 + EPS);
            s_inv [cg * 4 + 3] = rsqrtf(v3 + EPS);
        }
        __syncthreads();

        const float4 m  = ((const float4*)s_mean)[cg];
        const float4 iv = ((const float4*)s_inv)[cg];

        // ---- pass 2: each CTA normalizes ITS half (data it just read => L2-hot) ----
        const int smid   = start + (cnt >> 1);
        const int nstart = half ? smid : start;
        const int nend   = half ? end  : smid;

        r = nstart + rw;
        for (; r + 3 * ROWS_PER_ITER < nend; r += 4 * ROWS_PER_ITER) {
            float4 a = __ldcs(&xp[(size_t)r * CG + cg]);
            float4 b = __ldcs(&xp[(size_t)(r + 1 * ROWS_PER_ITER) * CG + cg]);
            float4 c = __ldcs(&xp[(size_t)(r + 2 * ROWS_PER_ITER) * CG + cg]);
            float4 d = __ldcs(&xp[(size_t)(r + 3 * ROWS_PER_ITER) * CG + cg]);
            a.x = (a.x - m.x) * iv.x * wv.x + bv.x;
            a.y = (a.y - m.y) * iv.y * wv.y + bv.y;
            a.z = (a.z - m.z) * iv.z * wv.z + bv.z;
            a.w = (a.w - m.w) * iv.w * wv.w + bv.w;
            __stcs(&op[(size_t)r * CG + cg], a);
            b.x = (b.x - m.x) * iv.x * wv.x + bv.x;
            b.y = (b.y - m.y) * iv.y * wv.y + bv.y;
            b.z = (b.z - m.z) * iv.z * wv.z + bv.z;
            b.w = (b.w - m.w) * iv.w * wv.w + bv.w;
            __stcs(&op[(size_t)(r + 1 * ROWS_PER_ITER) * CG + cg], b);
            c.x = (c.x - m.x) * iv.x * wv.x + bv.x;
            c.y = (c.y - m.y) * iv.y * wv.y + bv.y;
            c.z = (c.z - m.z) * iv.z * wv.z + bv.z;
            c.w = (c.w - m.w) * iv.w * wv.w + bv.w;
            __stcs(&op[(size_t)(r + 2 * ROWS_PER_ITER) * CG + cg], c);
            d.x = (d.x - m.x) * iv.x * wv.x + bv.x;
            d.y = (d.y - m.y) * iv.y * wv.y + bv.y;
            d.z = (d.z - m.z) * iv.z * wv.z + bv.z;
            d.w = (d.w - m.w) * iv.w * wv.w + bv.w;
            __stcs(&op[(size_t)(r + 3 * ROWS_PER_ITER) * CG + cg], d);
        }
        for (; r < nend; r += ROWS_PER_ITER) {
            float4 v = __ldcs(&xp[(size_t)r * CG + cg]);
            v.x = (v.x - m.x) * iv.x * wv.x + bv.x;
            v.y = (v.y - m.y) * iv.y * wv.y + bv.y;
            v.z = (v.z - m.z) * iv.z * wv.z + bv.z;
            v.w = (v.w - m.w) * iv.w * wv.w + bv.w;
            __stcs(&op[(size_t)r * CG + cg], v);
        }
        __syncthreads();   // protect smem before next segment's writes
    }
}

extern "C" void kernel_launch(void* const* d_in, const int* in_sizes, int n_in,
                              void* d_out, int out_size) {
    const float* x      = (const float*)d_in[0];
    const int*   batch  = (const int*)d_in[1];
    const float* weight = (const float*)d_in[2];
    const float* bias   = (const float*)d_in[3];
    float*       out    = (float*)d_out;
    const int n = in_sizes[1];   // number of rows (batch has one entry per row)

    graphnorm_kernel<<<GRID, THREADS>>>(x, batch, weight, bias, out, n);
}

// round 7
// speedup vs baseline: 1.6965x; 1.0980x over previous
#include <cuda_runtime.h>
#include <cuda_bf16.h>
#include <cstdint>

#define NUM_GRAPHS 512
#define C 128
#define CG (C / 4)        // 32 channel-groups of float4
#define THREADS 512
#define RPI (THREADS / CG)   // 16 rows per iteration
#define EPS 1e-5f
#define GRID 256
#define NPAIRS (GRID / 2)               // 128 clusters of 2
#define NSEG (NUM_GRAPHS / NPAIRS)      // 4 segments per cluster

__device__ __forceinline__ uint32_t smem_u32(const void* p) {
    uint32_t a;
    asm("{ .reg .u64 t; cvta.to.shared.u64 t, %1; cvt.u32.u64 %0, t; }"
        : "=r"(a) : "l"(p));
    return a;
}
__device__ __forceinline__ uint32_t mapa_rank(uint32_t addr, uint32_t rank) {
    uint32_t r;
    asm("mapa.shared::cluster.u32 %0, %1, %2;" : "=r"(r) : "r"(addr), "r"(rank));
    return r;
}
__device__ __forceinline__ float ld_dsmem_f32(uint32_t addr) {
    float v;
    asm volatile("ld.shared::cluster.f32 %0, [%1];" : "=f"(v) : "r"(addr));
    return v;
}
#define CLUSTER_SYNC() do { \
    asm volatile("barrier.cluster.arrive.aligned;" ::: "memory"); \
    asm volatile("barrier.cluster.wait.aligned;"   ::: "memory"); } while (0)

__global__ __launch_bounds__(THREADS, 2) __cluster_dims__(2, 1, 1)
void graphnorm_kernel(const float* __restrict__ x,
                      const int*   __restrict__ batch,
                      const float* __restrict__ weight,
                      const float* __restrict__ bias,
                      float* __restrict__ out,
                      int n) {
    const int t    = threadIdx.x;
    const int cg   = t & (CG - 1);   // channel group (4 consecutive channels)
    const int rw   = t >> 5;         // row lane (0..15)
    const int rank = blockIdx.x & 1; // cluster CTA rank
    const int pair = blockIdx.x >> 1;

    __shared__ int   s_bound[2 * NSEG];
    __shared__ float s_sum[RPI][C];     // 8 KB
    __shared__ float s_sq [RPI][C];     // 8 KB
    __shared__ float s_part[2][C];      // own half-segment partials (sum, sqsum)
    __shared__ float s_mean[C];
    __shared__ float s_inv [C];

    // ---- fused boundary search: threads 0..7 each find one boundary ----
    if (t < 2 * NSEG) {
        const int g = pair + (t >> 1) * NPAIRS + (t & 1);   // starts[g]
        int lo = 0, hi = n;
        while (lo < hi) {
            int mid = (lo + hi) >> 1;
            if (batch[mid] < g) lo = mid + 1; else hi = mid;
        }
        s_bound[t] = lo;
    }

    const float4 wv = ((const float4*)weight)[cg];
    const float4 bv = ((const float4*)bias)[cg];
    const float4* __restrict__ xp = (const float4*)x;
    float4* __restrict__       op = (float4*)out;

    const uint32_t part_base = smem_u32(&s_part[0][0]);
    const uint32_t peer_base = mapa_rank(part_base, rank ^ 1);

    __syncthreads();

    for (int i = 0; i < NSEG; i++) {
        const int start = s_bound[2 * i];
        const int end   = s_bound[2 * i + 1];
        const int cnt   = end - start;
        const int smid  = start + (cnt >> 1);
        const int h0    = rank ? smid : start;   // this CTA's half
        const int h1    = rank ? end  : smid;

        // ---- pass 1: accumulate over OWN half only (disjoint DRAM streams) ----
        float s0 = 0.f, s1 = 0.f, s2 = 0.f, s3 = 0.f;
        float q0 = 0.f, q1 = 0.f, q2 = 0.f, q3 = 0.f;
        int r = h0 + rw;
        for (; r + 3 * RPI < h1; r += 4 * RPI) {
            float4 a = xp[(size_t)r * CG + cg];
            float4 b = xp[(size_t)(r + 1 * RPI) * CG + cg];
            float4 c = xp[(size_t)(r + 2 * RPI) * CG + cg];
            float4 d = xp[(size_t)(r + 3 * RPI) * CG + cg];
            s0 += a.x; s1 += a.y; s2 += a.z; s3 += a.w;
            q0 += a.x * a.x; q1 += a.y * a.y; q2 += a.z * a.z; q3 += a.w * a.w;
            s0 += b.x; s1 += b.y; s2 += b.z; s3 += b.w;
            q0 += b.x * b.x; q1 += b.y * b.y; q2 += b.z * b.z; q3 += b.w * b.w;
            s0 += c.x; s1 += c.y; s2 += c.z; s3 += c.w;
            q0 += c.x * c.x; q1 += c.y * c.y; q2 += c.z * c.z; q3 += c.w * c.w;
            s0 += d.x; s1 += d.y; s2 += d.z; s3 += d.w;
            q0 += d.x * d.x; q1 += d.y * d.y; q2 += d.z * d.z; q3 += d.w * d.w;
        }
        for (; r < h1; r += RPI) {
            float4 v = xp[(size_t)r * CG + cg];
            s0 += v.x; s1 += v.y; s2 += v.z; s3 += v.w;
            q0 += v.x * v.x; q1 += v.y * v.y; q2 += v.z * v.z; q3 += v.w * v.w;
        }
        s_sum[rw][cg * 4 + 0] = s0; s_sum[rw][cg * 4 + 1] = s1;
        s_sum[rw][cg * 4 + 2] = s2; s_sum[rw][cg * 4 + 3] = s3;
        s_sq [rw][cg * 4 + 0] = q0; s_sq [rw][cg * 4 + 1] = q1;
        s_sq [rw][cg * 4 + 2] = q2; s_sq [rw][cg * 4 + 3] = q3;
        __syncthreads();

        // ---- reduce 16 lanes -> half-segment partials (fixed order) ----
        float S0, S1, S2, S3, Q0, Q1, Q2, Q3;
        if (rw == 0) {
            S0 = 0.f; S1 = 0.f; S2 = 0.f; S3 = 0.f;
            Q0 = 0.f; Q1 = 0.f; Q2 = 0.f; Q3 = 0.f;
            #pragma unroll
            for (int k = 0; k < RPI; k++) {
                S0 += s_sum[k][cg * 4 + 0]; S1 += s_sum[k][cg * 4 + 1];
                S2 += s_sum[k][cg * 4 + 2]; S3 += s_sum[k][cg * 4 + 3];
                Q0 += s_sq [k][cg * 4 + 0]; Q1 += s_sq [k][cg * 4 + 1];
                Q2 += s_sq [k][cg * 4 + 2]; Q3 += s_sq [k][cg * 4 + 3];
            }
            s_part[0][cg * 4 + 0] = S0; s_part[0][cg * 4 + 1] = S1;
            s_part[0][cg * 4 + 2] = S2; s_part[0][cg * 4 + 3] = S3;
            s_part[1][cg * 4 + 0] = Q0; s_part[1][cg * 4 + 1] = Q1;
            s_part[1][cg * 4 + 2] = Q2; s_part[1][cg * 4 + 3] = Q3;
        }
        CLUSTER_SYNC();   // partials visible cluster-wide

        // ---- combine own + peer partials (a+b commutative => identical in both CTAs) ----
        if (rw == 0) {
            const uint32_t po = peer_base + (uint32_t)(cg * 4) * 4u;
            float P0 = ld_dsmem_f32(po + 0);
            float P1 = ld_dsmem_f32(po + 4);
            float P2 = ld_dsmem_f32(po + 8);
            float P3 = ld_dsmem_f32(po + 12);
            float R0 = ld_dsmem_f32(po + C * 4 + 0);
            float R1 = ld_dsmem_f32(po + C * 4 + 4);
            float R2 = ld_dsmem_f32(po + C * 4 + 8);
            float R3 = ld_dsmem_f32(po + C * 4 + 12);
            const float invc = 1.0f / (float)max(cnt, 1);
            float m0 = (S0 + P0) * invc, m1 = (S1 + P1) * invc;
            float m2 = (S2 + P2) * invc, m3 = (S3 + P3) * invc;
            float v0 = (Q0 + R0) * invc - m0 * m0;
            float v1 = (Q1 + R1) * invc - m1 * m1;
            float v2 = (Q2 + R2) * invc - m2 * m2;
            float v3 = (Q3 + R3) * invc - m3 * m3;
            s_mean[cg * 4 + 0] = m0; s_mean[cg * 4 + 1] = m1;
            s_mean[cg * 4 + 2] = m2; s_mean[cg * 4 + 3] = m3;
            s_inv [cg * 4 + 0] = rsqrtf(v0 + EPS);
            s_inv [cg * 4 + 1] = rsqrtf(v1 + EPS);
            s_inv [cg * 4 + 2] = rsqrtf(v2 + EPS);
            s_inv [cg * 4 + 3] = rsqrtf(v3 + EPS);
        }
        CLUSTER_SYNC();   // s_mean/s_inv ready; peer done reading my s_part

        const float4 m  = ((const float4*)s_mean)[cg];
        const float4 iv = ((const float4*)s_inv)[cg];

        // ---- pass 2: normalize OWN half (L2-hot); evict-first loads, streaming stores ----
        r = h0 + rw;
        for (; r + 3 * RPI < h1; r += 4 * RPI) {
            float4 a = __ldcs(&xp[(size_t)r * CG + cg]);
            float4 b = __ldcs(&xp[(size_t)(r + 1 * RPI) * CG + cg]);
            float4 c = __ldcs(&xp[(size_t)(r + 2 * RPI) * CG + cg]);
            float4 d = __ldcs(&xp[(size_t)(r + 3 * RPI) * CG + cg]);
            a.x = (a.x - m.x) * iv.x * wv.x + bv.x;
            a.y = (a.y - m.y) * iv.y * wv.y + bv.y;
            a.z = (a.z - m.z) * iv.z * wv.z + bv.z;
            a.w = (a.w - m.w) * iv.w * wv.w + bv.w;
            __stcs(&op[(size_t)r * CG + cg], a);
            b.x = (b.x - m.x) * iv.x * wv.x + bv.x;
            b.y = (b.y - m.y) * iv.y * wv.y + bv.y;
            b.z = (b.z - m.z) * iv.z * wv.z + bv.z;
            b.w = (b.w - m.w) * iv.w * wv.w + bv.w;
            __stcs(&op[(size_t)(r + 1 * RPI) * CG + cg], b);
            c.x = (c.x - m.x) * iv.x * wv.x + bv.x;
            c.y = (c.y - m.y) * iv.y * wv.y + bv.y;
            c.z = (c.z - m.z) * iv.z * wv.z + bv.z;
            c.w = (c.w - m.w) * iv.w * wv.w + bv.w;
            __stcs(&op[(size_t)(r + 2 * RPI) * CG + cg], c);
            d.x = (d.x - m.x) * iv.x * wv.x + bv.x;
            d.y = (d.y - m.y) * iv.y * wv.y + bv.y;
            d.z = (d.z - m.z) * iv.z * wv.z + bv.z;
            d.w = (d.w - m.w) * iv.w * wv.w + bv.w;
            __stcs(&op[(size_t)(r + 3 * RPI) * CG + cg], d);
        }
        for (; r < h1; r += RPI) {
            float4 v = __ldcs(&xp[(size_t)r * CG + cg]);
            v.x = (v.x - m.x) * iv.x * wv.x + bv.x;
            v.y = (v.y - m.y) * iv.y * wv.y + bv.y;
            v.z = (v.z - m.z) * iv.z * wv.z + bv.z;
            v.w = (v.w - m.w) * iv.w * wv.w + bv.w;
            __stcs(&op[(size_t)r * CG + cg], v);
        }
        // no trailing barrier needed: next iteration's CLUSTER_SYNC serializes
        // all smem overwrites against stragglers.
        __syncthreads();   // protect s_sum before next iteration's pass-1 writes
    }
}

extern "C" void kernel_launch(void* const* d_in, const int* in_sizes, int n_in,
                              void* d_out, int out_size) {
    const float* x      = (const float*)d_in[0];
    const int*   batch  = (const int*)d_in[1];
    const float* weight = (const float*)d_in[2];
    const float* bias   = (const float*)d_in[3];
    float*       out    = (float*)d_out;
    const int n = in_sizes[1];   // number of rows

    graphnorm_kernel<<<GRID, THREADS>>>(x, batch, weight, bias, out, n);
}

// round 10
// speedup vs baseline: 1.7124x; 1.0094x over previous
#include <cuda_runtime.h>
#include <cuda_bf16.h>
#include <cstdint>

#define NUM_GRAPHS 512
#define C 128
#define CG (C / 4)           // 32 channel-groups of float4
#define THREADS 512
#define RPI (THREADS / CG)   // 16 rows per iteration
#define EPS 1e-5f
#define GRID 256
#define NPAIRS (GRID / 2)               // 128 clusters of 2
#define NSEG (NUM_GRAPHS / NPAIRS)      // 4 segments per cluster

__device__ __forceinline__ uint32_t smem_u32(const void* p) {
    uint32_t a;
    asm("{ .reg .u64 t; cvta.to.shared.u64 t, %1; cvt.u32.u64 %0, t; }"
        : "=r"(a) : "l"(p));
    return a;
}
__device__ __forceinline__ uint32_t mapa_rank(uint32_t addr, uint32_t rank) {
    uint32_t r;
    asm("mapa.shared::cluster.u32 %0, %1, %2;" : "=r"(r) : "r"(addr), "r"(rank));
    return r;
}
__device__ __forceinline__ void st_dsmem_f32(uint32_t addr, float v) {
    asm volatile("st.shared::cluster.f32 [%0], %1;" :: "r"(addr), "f"(v) : "memory");
}
__device__ __forceinline__ void mbar_arrive_release_cluster(uint32_t addr) {
    asm volatile("mbarrier.arrive.release.cluster.shared::cluster.b64 _, [%0];"
                 :: "r"(addr) : "memory");
}
__device__ __forceinline__ void mbar_wait_parity_cluster(uint32_t addr, uint32_t par) {
    uint32_t done;
    do {
        asm volatile(
            "{\n\t.reg .pred p;\n\t"
            "mbarrier.try_wait.parity.acquire.cluster.shared::cta.b64 p, [%1], %2;\n\t"
            "selp.b32 %0, 1, 0, p;\n\t}"
            : "=r"(done) : "r"(addr), "r"(par) : "memory");
    } while (!done);
}
#define CLUSTER_SYNC() do { \
    asm volatile("barrier.cluster.arrive.aligned;" ::: "memory"); \
    asm volatile("barrier.cluster.wait.aligned;"   ::: "memory"); } while (0)

__global__ __launch_bounds__(THREADS, 2) __cluster_dims__(2, 1, 1)
void graphnorm_kernel(const float* __restrict__ x,
                      const int*   __restrict__ batch,
                      const float* __restrict__ weight,
                      const float* __restrict__ bias,
                      float* __restrict__ out,
                      int n) {
    const int t    = threadIdx.x;
    const int cg   = t & (CG - 1);   // channel group (4 consecutive channels)
    const int rw   = t >> 5;         // row lane (0..15)
    const int rank = blockIdx.x & 1; // cluster CTA rank
    const int pair = blockIdx.x >> 1;

    __shared__ int   s_bound[2 * NSEG];
    __shared__ float s_sum[RPI][C];          // 8 KB
    __shared__ float s_sq [RPI][C];          // 8 KB
    __shared__ float s_recv[2][2][C];        // [parity][sum|sq][C], written by PEER
    __shared__ float s_mean[C];
    __shared__ float s_inv [C];
    __shared__ alignas(8) unsigned long long s_mbar;

    // ---- init: boundaries (threads 0..7) + mbarrier (thread 0) ----
    if (t < 2 * NSEG) {
        const int g = pair + (t >> 1) * NPAIRS + (t & 1);
        int lo = 0, hi = n;
        while (lo < hi) {
            int mid = (lo + hi) >> 1;
            if (batch[mid] < g) lo = mid + 1; else hi = mid;
        }
        s_bound[t] = lo;
    }
    const uint32_t mbar_local = smem_u32(&s_mbar);
    if (t == 0) {
        asm volatile("mbarrier.init.shared.b64 [%0], %1;"
                     :: "r"(mbar_local), "r"(32u) : "memory");   // 32 arrivals/phase
    }

    const float4 wv = ((const float4*)weight)[cg];
    const float4 bv = ((const float4*)bias)[cg];
    const float4* __restrict__ xp = (const float4*)x;
    float4* __restrict__       op = (float4*)out;

    const uint32_t recv_local = smem_u32(&s_recv[0][0][0]);
    const uint32_t recv_peer  = mapa_rank(recv_local, rank ^ 1);
    const uint32_t mbar_peer  = mapa_rank(mbar_local, rank ^ 1);

    __syncthreads();
    CLUSTER_SYNC();   // one-time: peer's mbarrier init visible before first push

    for (int i = 0; i < NSEG; i++) {
        const int par   = i & 1;
        const int start = s_bound[2 * i];
        const int end   = s_bound[2 * i + 1];
        const int cnt   = end - start;
        const int smid  = start + (cnt >> 1);
        const int h0    = rank ? smid : start;   // this CTA's half
        const int h1    = rank ? end  : smid;

        // ---- pass 1 (ascending): accumulate over OWN half ----
        float s0 = 0.f, s1 = 0.f, s2 = 0.f, s3 = 0.f;
        float q0 = 0.f, q1 = 0.f, q2 = 0.f, q3 = 0.f;
        int r = h0 + rw;
        for (; r + 3 * RPI < h1; r += 4 * RPI) {
            float4 a = xp[(size_t)r * CG + cg];
            float4 b = xp[(size_t)(r + 1 * RPI) * CG + cg];
            float4 c = xp[(size_t)(r + 2 * RPI) * CG + cg];
            float4 d = xp[(size_t)(r + 3 * RPI) * CG + cg];
            s0 += a.x; s1 += a.y; s2 += a.z; s3 += a.w;
            q0 += a.x * a.x; q1 += a.y * a.y; q2 += a.z * a.z; q3 += a.w * a.w;
            s0 += b.x; s1 += b.y; s2 += b.z; s3 += b.w;
            q0 += b.x * b.x; q1 += b.y * b.y; q2 += b.z * b.z; q3 += b.w * b.w;
            s0 += c.x; s1 += c.y; s2 += c.z; s3 += c.w;
            q0 += c.x * c.x; q1 += c.y * c.y; q2 += c.z * c.z; q3 += c.w * c.w;
            s0 += d.x; s1 += d.y; s2 += d.z; s3 += d.w;
            q0 += d.x * d.x; q1 += d.y * d.y; q2 += d.z * d.z; q3 += d.w * d.w;
        }
        for (; r < h1; r += RPI) {
            float4 v = xp[(size_t)r * CG + cg];
            s0 += v.x; s1 += v.y; s2 += v.z; s3 += v.w;
            q0 += v.x * v.x; q1 += v.y * v.y; q2 += v.z * v.z; q3 += v.w * v.w;
        }
        s_sum[rw][cg * 4 + 0] = s0; s_sum[rw][cg * 4 + 1] = s1;
        s_sum[rw][cg * 4 + 2] = s2; s_sum[rw][cg * 4 + 3] = s3;
        s_sq [rw][cg * 4 + 0] = q0; s_sq [rw][cg * 4 + 1] = q1;
        s_sq [rw][cg * 4 + 2] = q2; s_sq [rw][cg * 4 + 3] = q3;
        __syncthreads();

        // ---- warp 0: reduce, push partials to peer, wait for peer's, combine ----
        if (rw == 0) {
            float S0 = 0.f, S1 = 0.f, S2 = 0.f, S3 = 0.f;
            float Q0 = 0.f, Q1 = 0.f, Q2 = 0.f, Q3 = 0.f;
            #pragma unroll
            for (int k = 0; k < RPI; k++) {
                S0 += s_sum[k][cg * 4 + 0]; S1 += s_sum[k][cg * 4 + 1];
                S2 += s_sum[k][cg * 4 + 2]; S3 += s_sum[k][cg * 4 + 3];
                Q0 += s_sq [k][cg * 4 + 0]; Q1 += s_sq [k][cg * 4 + 1];
                Q2 += s_sq [k][cg * 4 + 2]; Q3 += s_sq [k][cg * 4 + 3];
            }
            // push my partials into peer's s_recv[par]
            const uint32_t dst = recv_peer + (uint32_t)par * (2 * C * 4)
                                           + (uint32_t)cg * 16u;
            st_dsmem_f32(dst +  0, S0); st_dsmem_f32(dst +  4, S1);
            st_dsmem_f32(dst +  8, S2); st_dsmem_f32(dst + 12, S3);
            st_dsmem_f32(dst + C * 4 +  0, Q0); st_dsmem_f32(dst + C * 4 +  4, Q1);
            st_dsmem_f32(dst + C * 4 +  8, Q2); st_dsmem_f32(dst + C * 4 + 12, Q3);
            mbar_arrive_release_cluster(mbar_peer);   // each of 32 threads arrives

            // wait for peer's 32 arrivals on MY barrier, then read local recv
            mbar_wait_parity_cluster(mbar_local, (uint32_t)par);
            float P0 = s_recv[par][0][cg * 4 + 0];
            float P1 = s_recv[par][0][cg * 4 + 1];
            float P2 = s_recv[par][0][cg * 4 + 2];
            float P3 = s_recv[par][0][cg * 4 + 3];
            float R0 = s_recv[par][1][cg * 4 + 0];
            float R1 = s_recv[par][1][cg * 4 + 1];
            float R2 = s_recv[par][1][cg * 4 + 2];
            float R3 = s_recv[par][1][cg * 4 + 3];

            const float invc = 1.0f / (float)max(cnt, 1);
            float m0 = (S0 + P0) * invc, m1 = (S1 + P1) * invc;
            float m2 = (S2 + P2) * invc, m3 = (S3 + P3) * invc;
            float v0 = (Q0 + R0) * invc - m0 * m0;
            float v1 = (Q1 + R1) * invc - m1 * m1;
            float v2 = (Q2 + R2) * invc - m2 * m2;
            float v3 = (Q3 + R3) * invc - m3 * m3;
            s_mean[cg * 4 + 0] = m0; s_mean[cg * 4 + 1] = m1;
            s_mean[cg * 4 + 2] = m2; s_mean[cg * 4 + 3] = m3;
            s_inv [cg * 4 + 0] = rsqrtf(v0 + EPS);
            s_inv [cg * 4 + 1] = rsqrtf(v1 + EPS);
            s_inv [cg * 4 + 2] = rsqrtf(v2 + EPS);
            s_inv [cg * 4 + 3] = rsqrtf(v3 + EPS);
        }
        __syncthreads();

        const float4 m  = ((const float4*)s_mean)[cg];
        const float4 iv = ((const float4*)s_inv)[cg];

        // ---- pass 2 (DESCENDING): most-recently-loaded rows first => L1/L2 hot ----
        const int rbeg = h0 + rw;
        const int span = h1 - rbeg;
        const int nIt  = (span > 0) ? ((span + RPI - 1) / RPI) : 0;
        const int nF   = nIt >> 2;
        for (int k = nIt - 1; k >= nF * 4; k--) {   // tail singles (top rows)
            int rr = rbeg + k * RPI;
            float4 v = __ldcs(&xp[(size_t)rr * CG + cg]);
            v.x = (v.x - m.x) * iv.x * wv.x + bv.x;
            v.y = (v.y - m.y) * iv.y * wv.y + bv.y;
            v.z = (v.z - m.z) * iv.z * wv.z + bv.z;
            v.w = (v.w - m.w) * iv.w * wv.w + bv.w;
            __stcs(&op[(size_t)rr * CG + cg], v);
        }
        for (int f = nF - 1; f >= 0; f--) {         // full 4-blocks, descending
            int rr = rbeg + 4 * f * RPI;
            float4 a = __ldcs(&xp[(size_t)(rr + 3 * RPI) * CG + cg]);
            float4 b = __ldcs(&xp[(size_t)(rr + 2 * RPI) * CG + cg]);
            float4 c = __ldcs(&xp[(size_t)(rr + 1 * RPI) * CG + cg]);
            float4 d = __ldcs(&xp[(size_t)rr * CG + cg]);
            a.x = (a.x - m.x) * iv.x * wv.x + bv.x;
            a.y = (a.y - m.y) * iv.y * wv.y + bv.y;
            a.z = (a.z - m.z) * iv.z * wv.z + bv.z;
            a.w = (a.w - m.w) * iv.w * wv.w + bv.w;
            __stcs(&op[(size_t)(rr + 3 * RPI) * CG + cg], a);
            b.x = (b.x - m.x) * iv.x * wv.x + bv.x;
            b.y = (b.y - m.y) * iv.y * wv.y + bv.y;
            b.z = (b.z - m.z) * iv.z * wv.z + bv.z;
            b.w = (b.w - m.w) * iv.w * wv.w + bv.w;
            __stcs(&op[(size_t)(rr + 2 * RPI) * CG + cg], b);
            c.x = (c.x - m.x) * iv.x * wv.x + bv.x;
            c.y = (c.y - m.y) * iv.y * wv.y + bv.y;
            c.z = (c.z - m.z) * iv.z * wv.z + bv.z;
            c.w = (c.w - m.w) * iv.w * wv.w + bv.w;
            __stcs(&op[(size_t)(rr + 1 * RPI) * CG + cg], c);
            d.x = (d.x - m.x) * iv.x * wv.x + bv.x;
            d.y = (d.y - m.y) * iv.y * wv.y + bv.y;
            d.z = (d.z - m.z) * iv.z * wv.z + bv.z;
            d.w = (d.w - m.w) * iv.w * wv.w + bv.w;
            __stcs(&op[(size_t)rr * CG + cg], d);
        }
        __syncthreads();   // protect s_sum/s_mean before next iteration
    }

    CLUSTER_SYNC();   // don't exit while peer may still target my smem
}

extern "C" void kernel_launch(void* const* d_in, const int* in_sizes, int n_in,
                              void* d_out, int out_size) {
    const float* x      = (const float*)d_in[0];
    const int*   batch  = (const int*)d_in[1];
    const float* weight = (const float*)d_in[2];
    const float* bias   = (const float*)d_in[3];
    float*       out    = (float*)d_out;
    const int n = in_sizes[1];

    graphnorm_kernel<<<GRID, THREADS>>>(x, batch, weight, bias, out, n);
}